// round 2
// baseline (speedup 1.0000x reference)
#include <cuda_runtime.h>
#include <math.h>

#define T_STEPS 128
#define NN 32
#define EE 512
#define INC 64
#define HID 128
#define SEQL 16
#define G4 512          // 4*HID
#define WPC 16          // windows per LSTM CTA
#define PPAD 144        // padded G1 rows (need 143 = T + SEQL - 1)

// ---------------- global scratch (no allocation allowed) ----------------
__device__ float d_H[T_STEPS * NN * HID];           // GCN output  [t][n][k]
__device__ float d_G1[NN * PPAD * G4];              // Wih1@H + biases, padded
__device__ float d_Wih1T[NN * HID * G4];            // [n][k][j]
__device__ float d_Whh1T[NN * HID * G4];
__device__ float d_Wih2T[NN * HID * G4];
__device__ float d_Whh2T[NN * HID * G4];
__device__ float d_WfcT[NN * HID * HID];            // [n][h][k2]

// ---------------- fast transcendentals (rel err ~1e-6, tol 1e-3) --------
__device__ __forceinline__ float sigf(float x) {
    return __fdividef(1.0f, 1.0f + __expf(-x));
}
__device__ __forceinline__ float tanh_f(float x) {
    float ax = fabsf(x);
    float e  = __expf(-2.0f * ax);             // in (0,1], no overflow
    float t  = __fdividef(1.0f - e, 1.0f + e);
    return copysignf(t, x);
}

// ---------------- weight transposes (coalesced smem-tiled) --------------
__global__ void transpose_kernel(const float* __restrict__ Wih1,
                                 const float* __restrict__ Whh1,
                                 const float* __restrict__ Wih2,
                                 const float* __restrict__ Whh2,
                                 const float* __restrict__ Wfc) {
    int n = blockIdx.x, m = blockIdx.y;
    const float* src; float* dst; int R, C;
    if      (m == 0) { src = Wih1; dst = d_Wih1T; R = G4;  C = HID; }
    else if (m == 1) { src = Whh1; dst = d_Whh1T; R = G4;  C = HID; }
    else if (m == 2) { src = Wih2; dst = d_Wih2T; R = G4;  C = HID; }
    else if (m == 3) { src = Whh2; dst = d_Whh2T; R = G4;  C = HID; }
    else             { src = Wfc;  dst = d_WfcT;  R = HID; C = HID; }
    src += (size_t)n * R * C; dst += (size_t)n * R * C;
    __shared__ float s[32][33];
    int tx = threadIdx.x & 31, ty = threadIdx.x >> 5;   // 256 threads
    for (int bi = 0; bi < R; bi += 32)
        for (int bj = 0; bj < C; bj += 32) {
            #pragma unroll
            for (int r = ty; r < 32; r += 8)
                s[r][tx] = src[(bi + r) * C + bj + tx];
            __syncthreads();
            #pragma unroll
            for (int r = ty; r < 32; r += 8)
                dst[(bj + r) * R + bi + tx] = s[tx][r];
            __syncthreads();
        }
}

// ---------------- per-timestep 2-layer GCN ------------------------------
// out = relu(A @ (relu(A @ (x W1) + b1)) W2 + b2), A = sym-normalized adj+I
__global__ __launch_bounds__(128) void gcn_kernel(
    const float* __restrict__ x, const int* __restrict__ ei,
    const float* __restrict__ W1, const float* __restrict__ b1,
    const float* __restrict__ W2, const float* __restrict__ b2) {
    int t = blockIdx.x, k = threadIdx.x;            // k = hidden dim owner
    __shared__ float xs[NN * INC];
    __shared__ float A[NN * NN];
    __shared__ float dinv[NN];
    __shared__ float h0s[NN * HID];
    __shared__ float h1s[NN * HID];

    for (int i = k; i < NN * INC; i += 128) xs[i] = x[t * NN * INC + i];
    for (int i = k; i < NN * NN; i += 128)  A[i] = 0.f;
    if (k < NN) dinv[k] = 1.0f;                     // self-loop in degree
    __syncthreads();

    const int* row = ei + t * 2 * EE;
    const int* col = row + EE;
    for (int e = k; e < EE; e += 128) atomicAdd(&dinv[col[e]], 1.0f);
    __syncthreads();
    if (k < NN) dinv[k] = rsqrtf(dinv[k]);
    __syncthreads();
    for (int e = k; e < EE; e += 128) {
        int r = row[e], c = col[e];
        atomicAdd(&A[c * NN + r], dinv[r] * dinv[c]);
    }
    if (k < NN) atomicAdd(&A[k * NN + k], dinv[k] * dinv[k]);  // self-loop
    __syncthreads();

    // layer 1: h0 = x @ W1
    float acc[NN];
    #pragma unroll
    for (int nn = 0; nn < NN; nn++) acc[nn] = 0.f;
    for (int c = 0; c < INC; c++) {
        float wv = W1[c * HID + k];
        #pragma unroll
        for (int nn = 0; nn < NN; nn++) acc[nn] += xs[nn * INC + c] * wv;
    }
    #pragma unroll
    for (int nn = 0; nn < NN; nn++) h0s[nn * HID + k] = acc[nn];
    __syncthreads();
    float bv = b1[k];
    #pragma unroll
    for (int nn = 0; nn < NN; nn++) {
        float s = bv;
        #pragma unroll
        for (int r = 0; r < NN; r++) s += A[nn * NN + r] * h0s[r * HID + k];
        h1s[nn * HID + k] = fmaxf(s, 0.f);
    }
    __syncthreads();

    // layer 2
    #pragma unroll
    for (int nn = 0; nn < NN; nn++) acc[nn] = 0.f;
    for (int c = 0; c < HID; c++) {
        float wv = W2[c * HID + k];
        #pragma unroll
        for (int nn = 0; nn < NN; nn++) acc[nn] += h1s[nn * HID + c] * wv;
    }
    #pragma unroll
    for (int nn = 0; nn < NN; nn++) h0s[nn * HID + k] = acc[nn];
    __syncthreads();
    bv = b2[k];
    #pragma unroll
    for (int nn = 0; nn < NN; nn++) {
        float s = bv;
        #pragma unroll
        for (int r = 0; r < NN; r++) s += A[nn * NN + r] * h0s[r * HID + k];
        d_H[(t * NN + nn) * HID + k] = fmaxf(s, 0.f);
    }
}

// ---------------- shared input-gate precompute --------------------------
// G1[n][p][j] = bih1+bhh1 + Wih1 @ H[p-15]   (p<15 -> bias only: zero input)
__global__ __launch_bounds__(256) void g1_kernel(
    const float* __restrict__ bih1, const float* __restrict__ bhh1) {
    int n = blockIdx.x, pc = blockIdx.y, tid = threadIdx.x;
    __shared__ float hs[32 * HID];
    for (int idx = tid; idx < 32 * HID; idx += 256) {
        int w = idx >> 7, kk = idx & 127;
        int p = pc * 32 + w;
        hs[idx] = (p >= 15 && p < 143) ? d_H[((p - 15) * NN + n) * HID + kk] : 0.f;
    }
    __syncthreads();
    int j0 = tid, j1 = tid + 256;
    float a0[32], a1[32];
    float bi0 = bih1[n * G4 + j0] + bhh1[n * G4 + j0];
    float bi1 = bih1[n * G4 + j1] + bhh1[n * G4 + j1];
    #pragma unroll
    for (int w = 0; w < 32; w++) { a0[w] = bi0; a1[w] = bi1; }
    const float* WT = d_Wih1T + (size_t)n * HID * G4;
    #pragma unroll 4
    for (int kk = 0; kk < HID; kk++) {
        float w0 = WT[kk * G4 + j0], w1 = WT[kk * G4 + j1];
        #pragma unroll
        for (int w = 0; w < 32; w++) {
            float hv = hs[w * HID + kk];
            a0[w] += w0 * hv; a1[w] += w1 * hv;
        }
    }
    #pragma unroll
    for (int w = 0; w < 32; w++) {
        int p = pc * 32 + w;
        if (p < 143) {
            d_G1[((size_t)n * PPAD + p) * G4 + j0] = a0[w];
            d_G1[((size_t)n * PPAD + p) * G4 + j1] = a1[w];
        }
    }
}

// ---------------- stacked LSTM over sliding windows + heads -------------
__global__ __launch_bounds__(256) void lstm_kernel(
    const float* __restrict__ bih2, const float* __restrict__ bhh2,
    const float* __restrict__ bfc,
    const float* __restrict__ Wout0, const float* __restrict__ bout0,
    const float* __restrict__ Wout1, const float* __restrict__ bout1,
    float* __restrict__ out) {
    int n = blockIdx.x, t0 = blockIdx.y * WPC, tid = threadIdx.x;
    __shared__ float h1s[WPC * HID], h2s[WPC * HID], tmp[WPC * HID];
    __shared__ float bias2[G4];

    for (int i = tid; i < WPC * HID; i += 256) { h1s[i] = 0.f; h2s[i] = 0.f; }
    for (int i = tid; i < G4; i += 256)
        bias2[i] = bih2[n * G4 + i] + bhh2[n * G4 + i];

    float c1r[WPC], c2r[WPC];
    #pragma unroll
    for (int w = 0; w < WPC; w++) { c1r[w] = 0.f; c2r[w] = 0.f; }

    const int j0 = tid, j1 = tid + 256, k = tid & 127;
    const float* Wh1 = d_Whh1T + (size_t)n * HID * G4;
    const float* Wi2 = d_Wih2T + (size_t)n * HID * G4;
    const float* Wh2 = d_Whh2T + (size_t)n * HID * G4;
    const float* G1n = d_G1 + (size_t)n * PPAD * G4;
    __syncthreads();

    for (int l = 0; l < SEQL; l++) {
        // ---- LSTM1: gates = G1[t0+w+l] + Whh1 @ h1 ----
        float a0[WPC], a1[WPC];
        #pragma unroll
        for (int w = 0; w < WPC; w++) {
            const float* g = G1n + (t0 + w + l) * G4;
            a0[w] = g[j0]; a1[w] = g[j1];
        }
        #pragma unroll 4
        for (int kk = 0; kk < HID; kk++) {
            float w0 = Wh1[kk * G4 + j0], w1 = Wh1[kk * G4 + j1];
            #pragma unroll
            for (int w = 0; w < WPC; w++) {
                float hv = h1s[w * HID + kk];
                a0[w] += w0 * hv; a1[w] += w1 * hv;
            }
        }
        __syncthreads();                       // all GEMM1 reads of h1s done
        if (tid < 128) {                       // owns (i,g) for dim k
            #pragma unroll
            for (int w = 0; w < WPC; w++)
                tmp[w * HID + k] = sigf(a0[w]) * tanh_f(a1[w]);
        }
        __syncthreads();
        if (tid >= 128) {                      // owns (f,o); c1 in registers
            #pragma unroll
            for (int w = 0; w < WPC; w++) {
                float c = sigf(a0[w]) * c1r[w] + tmp[w * HID + k];
                c1r[w] = c;
                h1s[w * HID + k] = sigf(a1[w]) * tanh_f(c);
            }
        }
        __syncthreads();

        // ---- LSTM2: gates = bias2 + Wih2 @ h1_new + Whh2 @ h2 ----
        #pragma unroll
        for (int w = 0; w < WPC; w++) { a0[w] = bias2[j0]; a1[w] = bias2[j1]; }
        #pragma unroll 2
        for (int kk = 0; kk < HID; kk++) {
            float wi0 = Wi2[kk * G4 + j0], wh0 = Wh2[kk * G4 + j0];
            float wi1 = Wi2[kk * G4 + j1], wh1 = Wh2[kk * G4 + j1];
            #pragma unroll
            for (int w = 0; w < WPC; w++) {
                float hv1 = h1s[w * HID + kk], hv2 = h2s[w * HID + kk];
                a0[w] += wi0 * hv1; a0[w] += wh0 * hv2;
                a1[w] += wi1 * hv1; a1[w] += wh1 * hv2;
            }
        }
        __syncthreads();
        if (tid < 128) {
            #pragma unroll
            for (int w = 0; w < WPC; w++)
                tmp[w * HID + k] = sigf(a0[w]) * tanh_f(a1[w]);
        }
        __syncthreads();
        if (tid >= 128) {
            #pragma unroll
            for (int w = 0; w < WPC; w++) {
                float c = sigf(a0[w]) * c2r[w] + tmp[w * HID + k];
                c2r[w] = c;
                h2s[w * HID + k] = sigf(a1[w]) * tanh_f(c);
            }
        }
        __syncthreads();
    }

    // ---- epilogue: last = relu(h2); fc = last@WfcT + bfc; two heads ----
    for (int i = tid; i < WPC * HID; i += 256) tmp[i] = fmaxf(h2s[i], 0.f);
    __syncthreads();
    {
        int k2 = tid & 127, wg = tid >> 7;     // each thread: 8 windows
        float facc[WPC / 2];
        float bv = bfc[n * HID + k2];
        #pragma unroll
        for (int i = 0; i < WPC / 2; i++) facc[i] = bv;
        const float* WfT = d_WfcT + (size_t)n * HID * HID;
        #pragma unroll 2
        for (int h = 0; h < HID; h++) {
            float wv = WfT[h * HID + k2];
            #pragma unroll
            for (int i = 0; i < WPC / 2; i++)
                facc[i] += tmp[(2 * i + wg) * HID + h] * wv;
        }
        #pragma unroll
        for (int i = 0; i < WPC / 2; i++)
            h1s[(2 * i + wg) * HID + k2] = facc[i];   // fc -> h1s (reuse)
    }
    __syncthreads();
    if (tid < WPC * 6) {
        int w = tid / 6, jj = tid % 6;
        const float* Wp; float bb;
        if (jj < 4) { Wp = Wout0 + n * 4 * HID + jj * HID;       bb = bout0[n * 4 + jj]; }
        else        { Wp = Wout1 + n * 2 * HID + (jj - 4) * HID; bb = bout1[n * 2 + (jj - 4)]; }
        float s = bb;
        #pragma unroll 4
        for (int kk = 0; kk < HID; kk++) s += Wp[kk] * h1s[w * HID + kk];
        int t = t0 + w;
        if (jj < 4) out[(t * NN + n) * 4 + jj] = s;
        else        out[T_STEPS * NN * 4 + (t * NN + n) * 2 + (jj - 4)] = s;
    }
}

// ------------------------------------------------------------------------
extern "C" void kernel_launch(void* const* d_in, const int* in_sizes, int n_in,
                              void* d_out, int out_size) {
    const float* x     = (const float*)d_in[0];
    const int*   ei    = (const int*)  d_in[1];
    // d_in[2] = masks (all ones; unused)
    const float* y     = (const float*)d_in[3];
    const float* W1    = (const float*)d_in[4];
    const float* b1    = (const float*)d_in[5];
    const float* W2    = (const float*)d_in[6];
    const float* b2    = (const float*)d_in[7];
    const float* Wih1  = (const float*)d_in[8];
    const float* Whh1  = (const float*)d_in[9];
    const float* bih1  = (const float*)d_in[10];
    const float* bhh1  = (const float*)d_in[11];
    const float* Wih2  = (const float*)d_in[12];
    const float* Whh2  = (const float*)d_in[13];
    const float* bih2  = (const float*)d_in[14];
    const float* bhh2  = (const float*)d_in[15];
    const float* Wfc   = (const float*)d_in[16];
    const float* bfc   = (const float*)d_in[17];
    const float* Wout0 = (const float*)d_in[18];
    const float* bout0 = (const float*)d_in[19];
    const float* Wout1 = (const float*)d_in[20];
    const float* bout1 = (const float*)d_in[21];
    float* out = (float*)d_out;

    transpose_kernel<<<dim3(32, 5), 256>>>(Wih1, Whh1, Wih2, Whh2, Wfc);
    gcn_kernel<<<128, 128>>>(x, ei, W1, b1, W2, b2);
    g1_kernel<<<dim3(32, 5), 256>>>(bih1, bhh1);
    lstm_kernel<<<dim3(32, 8), 256>>>(bih2, bhh2, bfc, Wout0, bout0, Wout1, bout1, out);

    // targets = y, appended after out0 (T*N*4) and out1 (T*N*2)
    cudaMemcpyAsync(out + T_STEPS * NN * 4 + T_STEPS * NN * 2, y,
                    T_STEPS * NN * 4 * sizeof(float), cudaMemcpyDeviceToDevice);
}

// round 3
// speedup vs baseline: 1.2446x; 1.2446x over previous
#include <cuda_runtime.h>
#include <math.h>

#define T_STEPS 128
#define NN 32
#define EE 512
#define INC 64
#define HID 128
#define SEQL 16
#define G4 512          // 4*HID
#define WPC 16          // windows per LSTM CTA
#define PPAD 144        // padded G1 rows (need 143 = T + SEQL - 1)
#define HS 20           // lstm smem row stride (floats): 16B-aligned, bank-spread
#define HS1 36          // g1 smem row stride (32 windows + pad)

typedef unsigned long long ull;

// ---------------- global scratch (no allocation allowed) ----------------
__device__ float d_H[T_STEPS * NN * HID];           // GCN output  [t][n][k]
__device__ float d_G1[NN * PPAD * G4];              // Wih1@H + biases, pair-packed j
__device__ float d_Wih1T[NN * HID * G4];            // [n][k][2*p+s], j = s*256+p
__device__ float d_Whh1T[NN * HID * G4];
__device__ float d_Wih2T[NN * HID * G4];
__device__ float d_Whh2T[NN * HID * G4];
__device__ float d_WfcT[NN * HID * HID];            // [n][h][k2]

// ---------------- f32x2 packed helpers ----------------------------------
__device__ __forceinline__ void ffma2(ull &d, ull a, ull b) {
    asm("fma.rn.f32x2 %0, %1, %2, %0;" : "+l"(d) : "l"(a), "l"(b));
}
__device__ __forceinline__ ull splat2(float x) {
    ull r; unsigned u = __float_as_uint(x);
    asm("mov.b64 %0, {%1, %1};" : "=l"(r) : "r"(u)); return r;
}
__device__ __forceinline__ ull pack2(float x, float y) {
    ull r; unsigned a = __float_as_uint(x), b = __float_as_uint(y);
    asm("mov.b64 %0, {%1, %2};" : "=l"(r) : "r"(a), "r"(b)); return r;
}
__device__ __forceinline__ float2 unpack2(ull v) {
    unsigned a, b;
    asm("mov.b64 {%0, %1}, %2;" : "=r"(a), "=r"(b) : "l"(v));
    return make_float2(__uint_as_float(a), __uint_as_float(b));
}

// ---------------- fast transcendentals (rel err ~1e-6, tol 1e-3) --------
__device__ __forceinline__ float sigf(float x) {
    return __fdividef(1.0f, 1.0f + __expf(-x));
}
__device__ __forceinline__ float tanh_f(float x) {
    float ax = fabsf(x);
    float e  = __expf(-2.0f * ax);             // in (0,1], no overflow
    float t  = __fdividef(1.0f - e, 1.0f + e);
    return copysignf(t, x);
}

// ---------------- weight transposes (pair-packed for LSTM mats) ---------
// LSTM mats: dst[n][kk*512 + 2*(j&255) + (j>>8)] = src[n][j][kk]
__global__ void transpose_kernel(const float* __restrict__ Wih1,
                                 const float* __restrict__ Whh1,
                                 const float* __restrict__ Wih2,
                                 const float* __restrict__ Whh2,
                                 const float* __restrict__ Wfc) {
    int n = blockIdx.x, m = blockIdx.y;
    __shared__ float s[32][33];
    int tx = threadIdx.x & 31, ty = threadIdx.x >> 5;   // 256 threads
    if (m == 4) {
        const float* src = Wfc + (size_t)n * HID * HID;
        float* dst = d_WfcT + (size_t)n * HID * HID;
        for (int bi = 0; bi < HID; bi += 32)
            for (int bj = 0; bj < HID; bj += 32) {
                #pragma unroll
                for (int r = ty; r < 32; r += 8)
                    s[r][tx] = src[(bi + r) * HID + bj + tx];
                __syncthreads();
                #pragma unroll
                for (int r = ty; r < 32; r += 8)
                    dst[(bj + r) * HID + bi + tx] = s[tx][r];
                __syncthreads();
            }
        return;
    }
    const float* src;
    float* dst;
    if      (m == 0) { src = Wih1; dst = d_Wih1T; }
    else if (m == 1) { src = Whh1; dst = d_Whh1T; }
    else if (m == 2) { src = Wih2; dst = d_Wih2T; }
    else             { src = Whh2; dst = d_Whh2T; }
    src += (size_t)n * G4 * HID; dst += (size_t)n * HID * G4;
    for (int bj = 0; bj < G4; bj += 32) {       // j blocks
        int slot = bj >> 8;                     // constant within block
        for (int bi = 0; bi < HID; bi += 32) {  // k blocks
            #pragma unroll
            for (int r = ty; r < 32; r += 8)
                s[r][tx] = src[(bj + r) * HID + bi + tx];
            __syncthreads();
            #pragma unroll
            for (int r = ty; r < 32; r += 8) {
                int p = (bj + tx) & 255;
                dst[(bi + r) * G4 + 2 * p + slot] = s[tx][r];
            }
            __syncthreads();
        }
    }
}

// ---------------- per-timestep 2-layer GCN ------------------------------
__global__ __launch_bounds__(128) void gcn_kernel(
    const float* __restrict__ x, const int* __restrict__ ei,
    const float* __restrict__ W1, const float* __restrict__ b1,
    const float* __restrict__ W2, const float* __restrict__ b2) {
    int t = blockIdx.x, k = threadIdx.x;
    __shared__ float xs[NN * INC];
    __shared__ float A[NN * NN];
    __shared__ float dinv[NN];
    __shared__ float h0s[NN * HID];
    __shared__ float h1s[NN * HID];

    for (int i = k; i < NN * INC; i += 128) xs[i] = x[t * NN * INC + i];
    for (int i = k; i < NN * NN; i += 128)  A[i] = 0.f;
    if (k < NN) dinv[k] = 1.0f;
    __syncthreads();

    const int* row = ei + t * 2 * EE;
    const int* col = row + EE;
    for (int e = k; e < EE; e += 128) atomicAdd(&dinv[col[e]], 1.0f);
    __syncthreads();
    if (k < NN) dinv[k] = rsqrtf(dinv[k]);
    __syncthreads();
    for (int e = k; e < EE; e += 128) {
        int r = row[e], c = col[e];
        atomicAdd(&A[c * NN + r], dinv[r] * dinv[c]);
    }
    if (k < NN) atomicAdd(&A[k * NN + k], dinv[k] * dinv[k]);
    __syncthreads();

    float acc[NN];
    #pragma unroll
    for (int nn = 0; nn < NN; nn++) acc[nn] = 0.f;
    for (int c = 0; c < INC; c++) {
        float wv = W1[c * HID + k];
        #pragma unroll
        for (int nn = 0; nn < NN; nn++) acc[nn] += xs[nn * INC + c] * wv;
    }
    #pragma unroll
    for (int nn = 0; nn < NN; nn++) h0s[nn * HID + k] = acc[nn];
    __syncthreads();
    float bv = b1[k];
    #pragma unroll
    for (int nn = 0; nn < NN; nn++) {
        float s = bv;
        #pragma unroll
        for (int r = 0; r < NN; r++) s += A[nn * NN + r] * h0s[r * HID + k];
        h1s[nn * HID + k] = fmaxf(s, 0.f);
    }
    __syncthreads();

    #pragma unroll
    for (int nn = 0; nn < NN; nn++) acc[nn] = 0.f;
    for (int c = 0; c < HID; c++) {
        float wv = W2[c * HID + k];
        #pragma unroll
        for (int nn = 0; nn < NN; nn++) acc[nn] += h1s[nn * HID + c] * wv;
    }
    #pragma unroll
    for (int nn = 0; nn < NN; nn++) h0s[nn * HID + k] = acc[nn];
    __syncthreads();
    bv = b2[k];
    #pragma unroll
    for (int nn = 0; nn < NN; nn++) {
        float s = bv;
        #pragma unroll
        for (int r = 0; r < NN; r++) s += A[nn * NN + r] * h0s[r * HID + k];
        d_H[(t * NN + nn) * HID + k] = fmaxf(s, 0.f);
    }
}

// ---------------- shared input-gate precompute (f32x2) ------------------
// G1[n][p][2*tid+{0,1}] = (bih1+bhh1)[j0/j1] + (Wih1 @ H[p-15])[j0/j1]
__global__ __launch_bounds__(256) void g1_kernel(
    const float* __restrict__ bih1, const float* __restrict__ bhh1) {
    int n = blockIdx.x, pc = blockIdx.y, tid = threadIdx.x;
    __shared__ float hs[HID * HS1];             // [kk][w], 32 windows
    for (int idx = tid; idx < 32 * HID; idx += 256) {
        int w = idx >> 7, kk = idx & 127;
        int p = pc * 32 + w;
        hs[kk * HS1 + w] = (p >= 15 && p < 143)
                         ? d_H[((p - 15) * NN + n) * HID + kk] : 0.f;
    }
    __syncthreads();

    float b0 = bih1[n * G4 + tid] + bhh1[n * G4 + tid];
    float b1v = bih1[n * G4 + tid + 256] + bhh1[n * G4 + tid + 256];
    ull acc0[16], acc1[16];
    #pragma unroll
    for (int q = 0; q < 16; q++) { acc0[q] = splat2(b0); acc1[q] = splat2(b1v); }

    const float* WT = d_Wih1T + (size_t)n * HID * G4;
    #pragma unroll 2
    for (int kk = 0; kk < HID; kk++) {
        float2 wp = *(const float2*)(WT + kk * G4 + 2 * tid);
        ull w0 = splat2(wp.x), w1 = splat2(wp.y);
        const ulonglong2* hv = (const ulonglong2*)(hs + kk * HS1);
        #pragma unroll
        for (int q = 0; q < 8; q++) {
            ulonglong2 v = hv[q];
            ffma2(acc0[2 * q],     w0, v.x);
            ffma2(acc1[2 * q],     w1, v.x);
            ffma2(acc0[2 * q + 1], w0, v.y);
            ffma2(acc1[2 * q + 1], w1, v.y);
        }
    }
    #pragma unroll
    for (int q = 0; q < 16; q++) {
        float2 u0 = unpack2(acc0[q]), u1 = unpack2(acc1[q]);
        int p = pc * 32 + 2 * q;
        if (p < 143)
            *(float2*)(d_G1 + ((size_t)n * PPAD + p) * G4 + 2 * tid)
                = make_float2(u0.x, u1.x);
        if (p + 1 < 143)
            *(float2*)(d_G1 + ((size_t)n * PPAD + p + 1) * G4 + 2 * tid)
                = make_float2(u0.y, u1.y);
    }
}

// ---------------- stacked LSTM over sliding windows + heads (f32x2) -----
__global__ __launch_bounds__(256, 2) void lstm_kernel(
    const float* __restrict__ bih2, const float* __restrict__ bhh2,
    const float* __restrict__ bfc,
    const float* __restrict__ Wout0, const float* __restrict__ bout0,
    const float* __restrict__ Wout1, const float* __restrict__ bout1,
    float* __restrict__ out) {
    int n = blockIdx.x, t0 = blockIdx.y * WPC, tid = threadIdx.x;
    __shared__ float h1s[HID * HS], h2s[HID * HS], tmp[HID * HS];  // [kk][w]
    __shared__ float c1s[HID * WPC], c2s[HID * WPC];
    __shared__ float bias2p[G4];

    for (int i = tid; i < HID * HS; i += 256) { h1s[i] = 0.f; h2s[i] = 0.f; }
    for (int i = tid; i < HID * WPC; i += 256) { c1s[i] = 0.f; c2s[i] = 0.f; }
    bias2p[2 * tid]     = bih2[n * G4 + tid]       + bhh2[n * G4 + tid];
    bias2p[2 * tid + 1] = bih2[n * G4 + tid + 256] + bhh2[n * G4 + tid + 256];

    const int k = tid & 127;
    const float* Wh1 = d_Whh1T + (size_t)n * HID * G4;
    const float* Wi2 = d_Wih2T + (size_t)n * HID * G4;
    const float* Wh2 = d_Whh2T + (size_t)n * HID * G4;
    const float* G1n = d_G1 + (size_t)n * PPAD * G4;
    __syncthreads();

    for (int l = 0; l < SEQL; l++) {
        // ---- LSTM1: gates = G1[t0+w+l] + Whh1 @ h1 ----
        ull acc0[8], acc1[8];
        #pragma unroll
        for (int q = 0; q < 8; q++) {
            int p = t0 + 2 * q + l;
            float2 ga = *(const float2*)(G1n + (size_t)p * G4 + 2 * tid);
            float2 gb = *(const float2*)(G1n + (size_t)(p + 1) * G4 + 2 * tid);
            acc0[q] = pack2(ga.x, gb.x);
            acc1[q] = pack2(ga.y, gb.y);
        }
        #pragma unroll 4
        for (int kk = 0; kk < HID; kk++) {
            float2 wp = *(const float2*)(Wh1 + kk * G4 + 2 * tid);
            ull w0 = splat2(wp.x), w1 = splat2(wp.y);
            const ulonglong2* hv = (const ulonglong2*)(h1s + kk * HS);
            #pragma unroll
            for (int q = 0; q < 4; q++) {
                ulonglong2 v = hv[q];
                ffma2(acc0[2 * q],     w0, v.x);
                ffma2(acc1[2 * q],     w1, v.x);
                ffma2(acc0[2 * q + 1], w0, v.y);
                ffma2(acc1[2 * q + 1], w1, v.y);
            }
        }
        float a0v[WPC], a1v[WPC];
        #pragma unroll
        for (int q = 0; q < 8; q++) {
            float2 u = unpack2(acc0[q]); a0v[2 * q] = u.x; a0v[2 * q + 1] = u.y;
            u = unpack2(acc1[q]);        a1v[2 * q] = u.x; a1v[2 * q + 1] = u.y;
        }
        __syncthreads();                       // all GEMM1 reads of h1s done
        if (tid < 128) {                       // owns (i,g)
            #pragma unroll
            for (int w = 0; w < WPC; w++)
                tmp[k * HS + w] = sigf(a0v[w]) * tanh_f(a1v[w]);
        }
        __syncthreads();
        if (tid >= 128) {                      // owns (f,o)
            #pragma unroll
            for (int w = 0; w < WPC; w++) {
                float c = sigf(a0v[w]) * c1s[k * WPC + w] + tmp[k * HS + w];
                c1s[k * WPC + w] = c;
                h1s[k * HS + w] = sigf(a1v[w]) * tanh_f(c);
            }
        }
        __syncthreads();

        // ---- LSTM2: gates = bias2 + Wih2 @ h1_new + Whh2 @ h2 ----
        {
            ull bi0 = splat2(bias2p[2 * tid]), bi1 = splat2(bias2p[2 * tid + 1]);
            #pragma unroll
            for (int q = 0; q < 8; q++) { acc0[q] = bi0; acc1[q] = bi1; }
        }
        #pragma unroll 2
        for (int kk = 0; kk < HID; kk++) {
            float2 wi = *(const float2*)(Wi2 + kk * G4 + 2 * tid);
            float2 wh = *(const float2*)(Wh2 + kk * G4 + 2 * tid);
            ull wi0 = splat2(wi.x), wi1 = splat2(wi.y);
            ull wh0 = splat2(wh.x), wh1 = splat2(wh.y);
            const ulonglong2* hv1 = (const ulonglong2*)(h1s + kk * HS);
            const ulonglong2* hv2 = (const ulonglong2*)(h2s + kk * HS);
            #pragma unroll
            for (int q = 0; q < 4; q++) {
                ulonglong2 v1 = hv1[q], v2 = hv2[q];
                ffma2(acc0[2 * q],     wi0, v1.x);
                ffma2(acc1[2 * q],     wi1, v1.x);
                ffma2(acc0[2 * q],     wh0, v2.x);
                ffma2(acc1[2 * q],     wh1, v2.x);
                ffma2(acc0[2 * q + 1], wi0, v1.y);
                ffma2(acc1[2 * q + 1], wi1, v1.y);
                ffma2(acc0[2 * q + 1], wh0, v2.y);
                ffma2(acc1[2 * q + 1], wh1, v2.y);
            }
        }
        #pragma unroll
        for (int q = 0; q < 8; q++) {
            float2 u = unpack2(acc0[q]); a0v[2 * q] = u.x; a0v[2 * q + 1] = u.y;
            u = unpack2(acc1[q]);        a1v[2 * q] = u.x; a1v[2 * q + 1] = u.y;
        }
        __syncthreads();                       // GEMM2 reads done; tmp reusable
        if (tid < 128) {
            #pragma unroll
            for (int w = 0; w < WPC; w++)
                tmp[k * HS + w] = sigf(a0v[w]) * tanh_f(a1v[w]);
        }
        __syncthreads();
        if (tid >= 128) {
            #pragma unroll
            for (int w = 0; w < WPC; w++) {
                float c = sigf(a0v[w]) * c2s[k * WPC + w] + tmp[k * HS + w];
                c2s[k * WPC + w] = c;
                h2s[k * HS + w] = sigf(a1v[w]) * tanh_f(c);
            }
        }
        __syncthreads();
    }

    // ---- epilogue: last = relu(h2); fc = last@WfcT + bfc; two heads ----
    for (int i = tid; i < HID * HS; i += 256) tmp[i] = fmaxf(h2s[i], 0.f);
    __syncthreads();
    {
        int k2 = tid & 127, wg = tid >> 7;     // each thread: 8 windows
        float facc[WPC / 2];
        float bv = bfc[n * HID + k2];
        #pragma unroll
        for (int i = 0; i < WPC / 2; i++) facc[i] = bv;
        const float* WfT = d_WfcT + (size_t)n * HID * HID;
        #pragma unroll 2
        for (int h = 0; h < HID; h++) {
            float wv = WfT[h * HID + k2];
            #pragma unroll
            for (int i = 0; i < WPC / 2; i++)
                facc[i] += tmp[h * HS + (2 * i + wg)] * wv;
        }
        __syncthreads();
        #pragma unroll
        for (int i = 0; i < WPC / 2; i++)
            h1s[k2 * HS + (2 * i + wg)] = facc[i];   // fc -> h1s (reuse)
    }
    __syncthreads();
    if (tid < WPC * 6) {
        int w = tid / 6, jj = tid % 6;
        const float* Wp; float bb;
        if (jj < 4) { Wp = Wout0 + n * 4 * HID + jj * HID;       bb = bout0[n * 4 + jj]; }
        else        { Wp = Wout1 + n * 2 * HID + (jj - 4) * HID; bb = bout1[n * 2 + (jj - 4)]; }
        float s = bb;
        #pragma unroll 4
        for (int kk = 0; kk < HID; kk++) s += Wp[kk] * h1s[kk * HS + w];
        int t = t0 + w;
        if (jj < 4) out[(t * NN + n) * 4 + jj] = s;
        else        out[T_STEPS * NN * 4 + (t * NN + n) * 2 + (jj - 4)] = s;
    }
}

// ------------------------------------------------------------------------
extern "C" void kernel_launch(void* const* d_in, const int* in_sizes, int n_in,
                              void* d_out, int out_size) {
    const float* x     = (const float*)d_in[0];
    const int*   ei    = (const int*)  d_in[1];
    const float* y     = (const float*)d_in[3];
    const float* W1    = (const float*)d_in[4];
    const float* b1    = (const float*)d_in[5];
    const float* W2    = (const float*)d_in[6];
    const float* b2    = (const float*)d_in[7];
    const float* Wih1  = (const float*)d_in[8];
    const float* Whh1  = (const float*)d_in[9];
    const float* bih1  = (const float*)d_in[10];
    const float* bhh1  = (const float*)d_in[11];
    const float* Wih2  = (const float*)d_in[12];
    const float* Whh2  = (const float*)d_in[13];
    const float* bih2  = (const float*)d_in[14];
    const float* bhh2  = (const float*)d_in[15];
    const float* Wfc   = (const float*)d_in[16];
    const float* bfc   = (const float*)d_in[17];
    const float* Wout0 = (const float*)d_in[18];
    const float* bout0 = (const float*)d_in[19];
    const float* Wout1 = (const float*)d_in[20];
    const float* bout1 = (const float*)d_in[21];
    float* out = (float*)d_out;

    transpose_kernel<<<dim3(32, 5), 256>>>(Wih1, Whh1, Wih2, Whh2, Wfc);
    gcn_kernel<<<128, 128>>>(x, ei, W1, b1, W2, b2);
    g1_kernel<<<dim3(32, 5), 256>>>(bih1, bhh1);
    lstm_kernel<<<dim3(32, 8), 256>>>(bih2, bhh2, bfc, Wout0, bout0, Wout1, bout1, out);

    cudaMemcpyAsync(out + T_STEPS * NN * 4 + T_STEPS * NN * 2, y,
                    T_STEPS * NN * 4 * sizeof(float), cudaMemcpyDeviceToDevice);
}

// round 4
// speedup vs baseline: 1.3231x; 1.0631x over previous
#include <cuda_runtime.h>
#include <math.h>

#define T_STEPS 128
#define NN 32
#define EE 512
#define INC 64
#define HID 128
#define SEQL 16
#define G4 512          // 4*HID
#define WPC 16          // windows per LSTM CTA (8 per half-block)
#define PPAD 144        // padded G1 rows (need 143 = T + SEQL - 1)
#define HS 20           // lstm/g1 smem row stride (floats): 16B-aligned

typedef unsigned long long ull;

// ---------------- global scratch (no allocation allowed) ----------------
__device__ float d_H[T_STEPS * NN * HID];           // GCN output  [t][n][k]
__device__ float d_G1[NN * PPAD * G4];              // [n][p][4*k+g]
__device__ float d_Wih1T[NN * HID * G4];            // [n][kk][4*k+g], row j=g*128+k
__device__ float d_Whh1T[NN * HID * G4];
__device__ float d_Wih2T[NN * HID * G4];
__device__ float d_Whh2T[NN * HID * G4];
__device__ float d_WfcT[NN * HID * HID];            // [n][h][k2]

// ---------------- f32x2 packed helpers ----------------------------------
__device__ __forceinline__ void ffma2(ull &d, ull a, ull b) {
    asm("fma.rn.f32x2 %0, %1, %2, %0;" : "+l"(d) : "l"(a), "l"(b));
}
__device__ __forceinline__ ull splat2(float x) {
    ull r; unsigned u = __float_as_uint(x);
    asm("mov.b64 %0, {%1, %1};" : "=l"(r) : "r"(u)); return r;
}
__device__ __forceinline__ ull pack2(float x, float y) {
    ull r; unsigned a = __float_as_uint(x), b = __float_as_uint(y);
    asm("mov.b64 %0, {%1, %2};" : "=l"(r) : "r"(a), "r"(b)); return r;
}
__device__ __forceinline__ float2 unpack2(ull v) {
    unsigned a, b;
    asm("mov.b64 {%0, %1}, %2;" : "=r"(a), "=r"(b) : "l"(v));
    return make_float2(__uint_as_float(a), __uint_as_float(b));
}

// ---------------- fast transcendentals (rel err ~1e-6, tol 1e-3) --------
__device__ __forceinline__ float sigf(float x) {
    return __fdividef(1.0f, 1.0f + __expf(-x));
}
__device__ __forceinline__ float tanh_f(float x) {
    float ax = fabsf(x);
    float e  = __expf(-2.0f * ax);             // in (0,1], no overflow
    float t  = __fdividef(1.0f - e, 1.0f + e);
    return copysignf(t, x);
}

// ---------------- weight transposes ------------------------------------
// LSTM mats: dst[n][kk*512 + 4*(j&127) + (j>>7)] = src[n][j][kk]
__global__ void transpose_kernel(const float* __restrict__ Wih1,
                                 const float* __restrict__ Whh1,
                                 const float* __restrict__ Wih2,
                                 const float* __restrict__ Whh2,
                                 const float* __restrict__ Wfc) {
    int n = blockIdx.x, m = blockIdx.y;
    __shared__ float s[32][33];
    int tx = threadIdx.x & 31, ty = threadIdx.x >> 5;   // 256 threads
    if (m == 4) {
        const float* src = Wfc + (size_t)n * HID * HID;
        float* dst = d_WfcT + (size_t)n * HID * HID;
        for (int bi = 0; bi < HID; bi += 32)
            for (int bj = 0; bj < HID; bj += 32) {
                #pragma unroll
                for (int r = ty; r < 32; r += 8)
                    s[r][tx] = src[(bi + r) * HID + bj + tx];
                __syncthreads();
                #pragma unroll
                for (int r = ty; r < 32; r += 8)
                    dst[(bj + r) * HID + bi + tx] = s[tx][r];
                __syncthreads();
            }
        return;
    }
    const float* src;
    float* dst;
    if      (m == 0) { src = Wih1; dst = d_Wih1T; }
    else if (m == 1) { src = Whh1; dst = d_Whh1T; }
    else if (m == 2) { src = Wih2; dst = d_Wih2T; }
    else             { src = Whh2; dst = d_Whh2T; }
    src += (size_t)n * G4 * HID; dst += (size_t)n * HID * G4;
    for (int bj = 0; bj < G4; bj += 32) {       // j blocks
        for (int bi = 0; bi < HID; bi += 32) {  // kk blocks
            #pragma unroll
            for (int r = ty; r < 32; r += 8)
                s[r][tx] = src[(bj + r) * HID + bi + tx];
            __syncthreads();
            #pragma unroll
            for (int r = ty; r < 32; r += 8) {
                int j = bj + tx;
                dst[(bi + r) * G4 + 4 * (j & 127) + (j >> 7)] = s[tx][r];
            }
            __syncthreads();
        }
    }
}

// ---------------- per-timestep 2-layer GCN ------------------------------
__global__ __launch_bounds__(128) void gcn_kernel(
    const float* __restrict__ x, const int* __restrict__ ei,
    const float* __restrict__ W1, const float* __restrict__ b1,
    const float* __restrict__ W2, const float* __restrict__ b2) {
    int t = blockIdx.x, k = threadIdx.x;
    __shared__ float xs[NN * INC];
    __shared__ float A[NN * NN];
    __shared__ float dinv[NN];
    __shared__ float h0s[NN * HID];
    __shared__ float h1s[NN * HID];

    for (int i = k; i < NN * INC; i += 128) xs[i] = x[t * NN * INC + i];
    for (int i = k; i < NN * NN; i += 128)  A[i] = 0.f;
    if (k < NN) dinv[k] = 1.0f;
    __syncthreads();

    const int* row = ei + t * 2 * EE;
    const int* col = row + EE;
    for (int e = k; e < EE; e += 128) atomicAdd(&dinv[col[e]], 1.0f);
    __syncthreads();
    if (k < NN) dinv[k] = rsqrtf(dinv[k]);
    __syncthreads();
    for (int e = k; e < EE; e += 128) {
        int r = row[e], c = col[e];
        atomicAdd(&A[c * NN + r], dinv[r] * dinv[c]);
    }
    if (k < NN) atomicAdd(&A[k * NN + k], dinv[k] * dinv[k]);
    __syncthreads();

    float acc[NN];
    #pragma unroll
    for (int nn = 0; nn < NN; nn++) acc[nn] = 0.f;
    for (int c = 0; c < INC; c++) {
        float wv = W1[c * HID + k];
        #pragma unroll
        for (int nn = 0; nn < NN; nn++) acc[nn] += xs[nn * INC + c] * wv;
    }
    #pragma unroll
    for (int nn = 0; nn < NN; nn++) h0s[nn * HID + k] = acc[nn];
    __syncthreads();
    float bv = b1[k];
    #pragma unroll
    for (int nn = 0; nn < NN; nn++) {
        float s = bv;
        #pragma unroll
        for (int r = 0; r < NN; r++) s += A[nn * NN + r] * h0s[r * HID + k];
        h1s[nn * HID + k] = fmaxf(s, 0.f);
    }
    __syncthreads();

    #pragma unroll
    for (int nn = 0; nn < NN; nn++) acc[nn] = 0.f;
    for (int c = 0; c < HID; c++) {
        float wv = W2[c * HID + k];
        #pragma unroll
        for (int nn = 0; nn < NN; nn++) acc[nn] += h1s[nn * HID + c] * wv;
    }
    #pragma unroll
    for (int nn = 0; nn < NN; nn++) h0s[nn * HID + k] = acc[nn];
    __syncthreads();
    bv = b2[k];
    #pragma unroll
    for (int nn = 0; nn < NN; nn++) {
        float s = bv;
        #pragma unroll
        for (int r = 0; r < NN; r++) s += A[nn * NN + r] * h0s[r * HID + k];
        d_H[(t * NN + nn) * HID + k] = fmaxf(s, 0.f);
    }
}

// ---------------- shared input-gate precompute (4-gate f32x2) ------------
// G1[n][p][4k+g] = (bih1+bhh1)[g*128+k] + (Wih1 @ H[p-15])[g*128+k]
__global__ __launch_bounds__(128) void g1_kernel(
    const float* __restrict__ bih1, const float* __restrict__ bhh1) {
    int n = blockIdx.x, pc = blockIdx.y, k = threadIdx.x;   // 16 windows/CTA
    __shared__ float hs[HID * HS];              // [kk][w], 16 windows
    for (int idx = k; idx < 16 * HID; idx += 128) {
        int w = idx >> 7, kk = idx & 127;
        int p = pc * 16 + w;
        hs[kk * HS + w] = (p >= 15 && p < 143)
                        ? d_H[((p - 15) * NN + n) * HID + kk] : 0.f;
    }
    __syncthreads();

    ull acc[4][8];
    #pragma unroll
    for (int g = 0; g < 4; g++) {
        ull b = splat2(bih1[n * G4 + g * HID + k] + bhh1[n * G4 + g * HID + k]);
        #pragma unroll
        for (int q = 0; q < 8; q++) acc[g][q] = b;
    }
    const float* WT = d_Wih1T + (size_t)n * HID * G4;
    #pragma unroll 2
    for (int kk = 0; kk < HID; kk++) {
        float4 wv = *(const float4*)(WT + kk * G4 + 4 * k);
        ull w0 = splat2(wv.x), w1 = splat2(wv.y), w2 = splat2(wv.z), w3 = splat2(wv.w);
        const ulonglong2* hv = (const ulonglong2*)(hs + kk * HS);
        #pragma unroll
        for (int q2 = 0; q2 < 4; q2++) {
            ulonglong2 v = hv[q2];
            ffma2(acc[0][2 * q2],     w0, v.x); ffma2(acc[1][2 * q2],     w1, v.x);
            ffma2(acc[2][2 * q2],     w2, v.x); ffma2(acc[3][2 * q2],     w3, v.x);
            ffma2(acc[0][2 * q2 + 1], w0, v.y); ffma2(acc[1][2 * q2 + 1], w1, v.y);
            ffma2(acc[2][2 * q2 + 1], w2, v.y); ffma2(acc[3][2 * q2 + 1], w3, v.y);
        }
    }
    #pragma unroll
    for (int q = 0; q < 8; q++) {
        float2 u0 = unpack2(acc[0][q]), u1 = unpack2(acc[1][q]);
        float2 u2 = unpack2(acc[2][q]), u3 = unpack2(acc[3][q]);
        int p = pc * 16 + 2 * q;
        if (p < 143)
            *(float4*)(d_G1 + ((size_t)n * PPAD + p) * G4 + 4 * k)
                = make_float4(u0.x, u1.x, u2.x, u3.x);
        if (p + 1 < 143)
            *(float4*)(d_G1 + ((size_t)n * PPAD + p + 1) * G4 + 4 * k)
                = make_float4(u0.y, u1.y, u2.y, u3.y);
    }
}

// ---------------- stacked LSTM: 4-gate-per-thread, half-split windows ----
__global__ __launch_bounds__(256, 2) void lstm_kernel(
    const float* __restrict__ bih2, const float* __restrict__ bhh2,
    const float* __restrict__ bfc,
    const float* __restrict__ Wout0, const float* __restrict__ bout0,
    const float* __restrict__ Wout1, const float* __restrict__ bout1,
    float* __restrict__ out) {
    int n = blockIdx.x, t0 = blockIdx.y * WPC, tid = threadIdx.x;
    const int k = tid & 127, hf = tid >> 7;     // half-block: windows hf*8..hf*8+7
    const int wbase = hf * 8;
    __shared__ float h1s[HID * HS], h2s[HID * HS];   // [kk][w], w<16

    for (int i = tid; i < HID * HS; i += 256) { h1s[i] = 0.f; h2s[i] = 0.f; }

    // bias2 splats, persistent in registers
    ull bi2[4];
    #pragma unroll
    for (int g = 0; g < 4; g++)
        bi2[g] = splat2(bih2[n * G4 + g * HID + k] + bhh2[n * G4 + g * HID + k]);

    float c1[8], c2[8];
    #pragma unroll
    for (int w = 0; w < 8; w++) { c1[w] = 0.f; c2[w] = 0.f; }

    const float* Wh1 = d_Whh1T + (size_t)n * HID * G4;
    const float* Wi2 = d_Wih2T + (size_t)n * HID * G4;
    const float* Wh2 = d_Whh2T + (size_t)n * HID * G4;
    const float* G1n = d_G1 + (size_t)n * PPAD * G4;
    __syncthreads();

    for (int l = 0; l < SEQL; l++) {
        // ---- LSTM1: gates = G1[t0+w+l] + Whh1 @ h1 ----
        ull acc[4][4];
        #pragma unroll
        for (int q = 0; q < 4; q++) {
            int p0 = t0 + wbase + 2 * q + l;
            float4 A = *(const float4*)(G1n + (size_t)p0 * G4 + 4 * k);
            float4 B = *(const float4*)(G1n + (size_t)(p0 + 1) * G4 + 4 * k);
            acc[0][q] = pack2(A.x, B.x); acc[1][q] = pack2(A.y, B.y);
            acc[2][q] = pack2(A.z, B.z); acc[3][q] = pack2(A.w, B.w);
        }
        #pragma unroll 4
        for (int kk = 0; kk < HID; kk++) {
            float4 wv = *(const float4*)(Wh1 + kk * G4 + 4 * k);
            ull w0 = splat2(wv.x), w1 = splat2(wv.y), w2 = splat2(wv.z), w3 = splat2(wv.w);
            const ulonglong2* hv = (const ulonglong2*)(h1s + kk * HS + wbase);
            ulonglong2 v0 = hv[0], v1 = hv[1];
            ffma2(acc[0][0], w0, v0.x); ffma2(acc[1][0], w1, v0.x);
            ffma2(acc[2][0], w2, v0.x); ffma2(acc[3][0], w3, v0.x);
            ffma2(acc[0][1], w0, v0.y); ffma2(acc[1][1], w1, v0.y);
            ffma2(acc[2][1], w2, v0.y); ffma2(acc[3][1], w3, v0.y);
            ffma2(acc[0][2], w0, v1.x); ffma2(acc[1][2], w1, v1.x);
            ffma2(acc[2][2], w2, v1.x); ffma2(acc[3][2], w3, v1.x);
            ffma2(acc[0][3], w0, v1.y); ffma2(acc[1][3], w1, v1.y);
            ffma2(acc[2][3], w2, v1.y); ffma2(acc[3][3], w3, v1.y);
        }
        __syncthreads();                       // all reads of h1s done
        {
            float hrow[8];
            #pragma unroll
            for (int q = 0; q < 4; q++) {
                float2 iv = unpack2(acc[0][q]), fv = unpack2(acc[1][q]);
                float2 gv = unpack2(acc[2][q]), ov = unpack2(acc[3][q]);
                float c;
                c = sigf(fv.x) * c1[2 * q]     + sigf(iv.x) * tanh_f(gv.x);
                c1[2 * q] = c;     hrow[2 * q]     = sigf(ov.x) * tanh_f(c);
                c = sigf(fv.y) * c1[2 * q + 1] + sigf(iv.y) * tanh_f(gv.y);
                c1[2 * q + 1] = c; hrow[2 * q + 1] = sigf(ov.y) * tanh_f(c);
            }
            *(float4*)(h1s + k * HS + wbase)     = make_float4(hrow[0], hrow[1], hrow[2], hrow[3]);
            *(float4*)(h1s + k * HS + wbase + 4) = make_float4(hrow[4], hrow[5], hrow[6], hrow[7]);
        }
        __syncthreads();

        // ---- LSTM2: gates = bias2 + Wih2 @ h1_new + Whh2 @ h2 ----
        #pragma unroll
        for (int g = 0; g < 4; g++) {
            #pragma unroll
            for (int q = 0; q < 4; q++) acc[g][q] = bi2[g];
        }
        #pragma unroll 2
        for (int kk = 0; kk < HID; kk++) {
            float4 wi = *(const float4*)(Wi2 + kk * G4 + 4 * k);
            float4 wh = *(const float4*)(Wh2 + kk * G4 + 4 * k);
            ull wi0 = splat2(wi.x), wi1 = splat2(wi.y), wi2s = splat2(wi.z), wi3 = splat2(wi.w);
            ull wh0 = splat2(wh.x), wh1 = splat2(wh.y), wh2s = splat2(wh.z), wh3 = splat2(wh.w);
            const ulonglong2* hv1 = (const ulonglong2*)(h1s + kk * HS + wbase);
            const ulonglong2* hv2 = (const ulonglong2*)(h2s + kk * HS + wbase);
            ulonglong2 a0 = hv1[0], a1 = hv1[1], b0 = hv2[0], b1 = hv2[1];
            ffma2(acc[0][0], wi0, a0.x); ffma2(acc[1][0], wi1, a0.x);
            ffma2(acc[2][0], wi2s, a0.x); ffma2(acc[3][0], wi3, a0.x);
            ffma2(acc[0][0], wh0, b0.x); ffma2(acc[1][0], wh1, b0.x);
            ffma2(acc[2][0], wh2s, b0.x); ffma2(acc[3][0], wh3, b0.x);
            ffma2(acc[0][1], wi0, a0.y); ffma2(acc[1][1], wi1, a0.y);
            ffma2(acc[2][1], wi2s, a0.y); ffma2(acc[3][1], wi3, a0.y);
            ffma2(acc[0][1], wh0, b0.y); ffma2(acc[1][1], wh1, b0.y);
            ffma2(acc[2][1], wh2s, b0.y); ffma2(acc[3][1], wh3, b0.y);
            ffma2(acc[0][2], wi0, a1.x); ffma2(acc[1][2], wi1, a1.x);
            ffma2(acc[2][2], wi2s, a1.x); ffma2(acc[3][2], wi3, a1.x);
            ffma2(acc[0][2], wh0, b1.x); ffma2(acc[1][2], wh1, b1.x);
            ffma2(acc[2][2], wh2s, b1.x); ffma2(acc[3][2], wh3, b1.x);
            ffma2(acc[0][3], wi0, a1.y); ffma2(acc[1][3], wi1, a1.y);
            ffma2(acc[2][3], wi2s, a1.y); ffma2(acc[3][3], wi3, a1.y);
            ffma2(acc[0][3], wh0, b1.y); ffma2(acc[1][3], wh1, b1.y);
            ffma2(acc[2][3], wh2s, b1.y); ffma2(acc[3][3], wh3, b1.y);
        }
        __syncthreads();                       // all reads of h2s done
        {
            float hrow[8];
            #pragma unroll
            for (int q = 0; q < 4; q++) {
                float2 iv = unpack2(acc[0][q]), fv = unpack2(acc[1][q]);
                float2 gv = unpack2(acc[2][q]), ov = unpack2(acc[3][q]);
                float c;
                c = sigf(fv.x) * c2[2 * q]     + sigf(iv.x) * tanh_f(gv.x);
                c2[2 * q] = c;     hrow[2 * q]     = sigf(ov.x) * tanh_f(c);
                c = sigf(fv.y) * c2[2 * q + 1] + sigf(iv.y) * tanh_f(gv.y);
                c2[2 * q + 1] = c; hrow[2 * q + 1] = sigf(ov.y) * tanh_f(c);
            }
            *(float4*)(h2s + k * HS + wbase)     = make_float4(hrow[0], hrow[1], hrow[2], hrow[3]);
            *(float4*)(h2s + k * HS + wbase + 4) = make_float4(hrow[4], hrow[5], hrow[6], hrow[7]);
        }
        __syncthreads();
    }

    // ---- epilogue: last = relu(h2); fc = last@WfcT + bfc; two heads ----
    for (int i = tid; i < HID * HS; i += 256) h1s[i] = fmaxf(h2s[i], 0.f);
    __syncthreads();
    {
        ull facc[4];
        ull bv = splat2(bfc[n * HID + k]);
        #pragma unroll
        for (int q = 0; q < 4; q++) facc[q] = bv;
        const float* WfT = d_WfcT + (size_t)n * HID * HID;
        #pragma unroll 2
        for (int h = 0; h < HID; h++) {
            ull wv = splat2(WfT[h * HID + k]);
            const ulonglong2* hv = (const ulonglong2*)(h1s + h * HS + wbase);
            ulonglong2 v0 = hv[0], v1 = hv[1];
            ffma2(facc[0], wv, v0.x); ffma2(facc[1], wv, v0.y);
            ffma2(facc[2], wv, v1.x); ffma2(facc[3], wv, v1.y);
        }
        __syncthreads();
        #pragma unroll
        for (int q = 0; q < 4; q++) {
            float2 u = unpack2(facc[q]);
            h2s[k * HS + wbase + 2 * q]     = u.x;
            h2s[k * HS + wbase + 2 * q + 1] = u.y;
        }
    }
    __syncthreads();
    if (tid < WPC * 6) {
        int w = tid / 6, jj = tid % 6;
        const float* Wp; float bb;
        if (jj < 4) { Wp = Wout0 + n * 4 * HID + jj * HID;       bb = bout0[n * 4 + jj]; }
        else        { Wp = Wout1 + n * 2 * HID + (jj - 4) * HID; bb = bout1[n * 2 + (jj - 4)]; }
        float s = bb;
        #pragma unroll 4
        for (int kk = 0; kk < HID; kk++) s += Wp[kk] * h2s[kk * HS + w];
        int t = t0 + w;
        if (jj < 4) out[(t * NN + n) * 4 + jj] = s;
        else        out[T_STEPS * NN * 4 + (t * NN + n) * 2 + (jj - 4)] = s;
    }
}

// ------------------------------------------------------------------------
extern "C" void kernel_launch(void* const* d_in, const int* in_sizes, int n_in,
                              void* d_out, int out_size) {
    const float* x     = (const float*)d_in[0];
    const int*   ei    = (const int*)  d_in[1];
    const float* y     = (const float*)d_in[3];
    const float* W1    = (const float*)d_in[4];
    const float* b1    = (const float*)d_in[5];
    const float* W2    = (const float*)d_in[6];
    const float* b2    = (const float*)d_in[7];
    const float* Wih1  = (const float*)d_in[8];
    const float* Whh1  = (const float*)d_in[9];
    const float* bih1  = (const float*)d_in[10];
    const float* bhh1  = (const float*)d_in[11];
    const float* Wih2  = (const float*)d_in[12];
    const float* Whh2  = (const float*)d_in[13];
    const float* bih2  = (const float*)d_in[14];
    const float* bhh2  = (const float*)d_in[15];
    const float* Wfc   = (const float*)d_in[16];
    const float* bfc   = (const float*)d_in[17];
    const float* Wout0 = (const float*)d_in[18];
    const float* bout0 = (const float*)d_in[19];
    const float* Wout1 = (const float*)d_in[20];
    const float* bout1 = (const float*)d_in[21];
    float* out = (float*)d_out;

    transpose_kernel<<<dim3(32, 5), 256>>>(Wih1, Whh1, Wih2, Whh2, Wfc);
    gcn_kernel<<<128, 128>>>(x, ei, W1, b1, W2, b2);
    g1_kernel<<<dim3(32, 9), 128>>>(bih1, bhh1);
    lstm_kernel<<<dim3(32, 8), 256>>>(bih2, bhh2, bfc, Wout0, bout0, Wout1, bout1, out);

    cudaMemcpyAsync(out + T_STEPS * NN * 4 + T_STEPS * NN * 2, y,
                    T_STEPS * NN * 4 * sizeof(float), cudaMemcpyDeviceToDevice);
}